// round 7
// baseline (speedup 1.0000x reference)
#include <cuda_runtime.h>
#include <cstdint>
#include <math.h>

#define Bn 8
#define Nn 1024
#define Dn 1024
#define Hn 4096
#define En 16
#define CAP 80
#define SPLITK 4

#define NT 128      // block tile N
#define KT 32       // block tile K

// Fragment-packed smem (u32 units), double buffered.
// A: [2 k16][5 mt] tiles, tile = 2 chunks x 32 lanes x 4 u32 = 256, stride 260
// B: [2 k16][16 nt] tiles, tile = 32 lanes x 4 u32 (bh0,bl0,bh1,bl1) = 128, stride 132
#define ATS 260
#define BTS 132
#define OFF_B 2600                    // 10 * ATS
#define BUF_U32 (OFF_B + 32 * BTS)    // 6824
#define SMEM_BYTES (2 * BUF_U32 * 4)  // 54592

__device__ float g_hidden[(size_t)Bn * CAP * Hn];
__device__ float g_partial[(size_t)SPLITK * Bn * CAP * Dn];

__device__ __forceinline__ float gelu_exact(float x) {
    return 0.5f * x * (1.0f + erff(x * 0.70710678118654752440f));
}

// Split two f32 into packed bf16x2 hi (truncated, x in low half) and lo (residual).
__device__ __forceinline__ void split2(float x, float y, uint32_t& hi, uint32_t& lo) {
    uint32_t bx = __float_as_uint(x), by = __float_as_uint(y);
    asm("prmt.b32 %0, %1, %2, 0x7632;" : "=r"(hi) : "r"(bx), "r"(by));
    float lx = x - __uint_as_float(bx & 0xFFFF0000u);
    float ly = y - __uint_as_float(by & 0xFFFF0000u);
    asm("cvt.rn.bf16x2.f32 %0, %1, %2;" : "=r"(lo) : "f"(ly), "f"(lx));
}

__device__ __forceinline__ void mma_bf16(
    float* acc, uint32_t a0, uint32_t a1, uint32_t a2, uint32_t a3,
    uint32_t b0, uint32_t b1)
{
    asm volatile(
        "mma.sync.aligned.m16n8k16.row.col.f32.bf16.bf16.f32 "
        "{%0,%1,%2,%3}, {%4,%5,%6,%7}, {%8,%9}, {%0,%1,%2,%3};"
        : "+f"(acc[0]), "+f"(acc[1]), "+f"(acc[2]), "+f"(acc[3])
        : "r"(a0), "r"(a1), "r"(a2), "r"(a3), "r"(b0), "r"(b1));
}

// ---------------------------------------------------------------------------
// Core: Out[0:80, n0:n0+128] = A[80 x K] * B[K x N] over k in
// [kbase, kbase+ktiles*32). 3-term bf16-split mma.sync, fp32 accum.
// 320 threads = 10 warps (5 M x 2 N), warp tile 16x64. Fragment-packed smem.
// ---------------------------------------------------------------------------
template <bool GELU>
__device__ __forceinline__ void gemm_core(
    const float* __restrict__ A, int lda,
    const float* __restrict__ Bg, int ldb,
    int n0, int kbase, int ktiles,
    float* __restrict__ Out, int ldo)
{
    extern __shared__ uint32_t Sm[];
    const int tid = threadIdx.x;
    const int wid = tid >> 5;
    const int lid = tid & 31;
    const int wm = wid >> 1;        // 0..4
    const int wn = wid & 1;         // 0..1
    const int g = lid >> 2;         // 0..7
    const int c = lid & 3;          // 0..3

    // ---- producer mappings ----
    // A: 80 rows x 8 float4 (32 k) = 640 float4 -> 2 per thread
    int a_addr[2];
    const float* a_ptr[2];
    #pragma unroll
    for (int r = 0; r < 2; r++) {
        int idx = tid + r * 320;
        int m = idx >> 3;          // 0..79
        int s = idx & 7;           // float4 within row (pairs 2s,2s+1)
        int k16 = s >> 2;
        int pl0 = (s & 3) * 2;     // even local pair
        int mt = m >> 4, mrow = m & 15;
        int j0 = (mrow >> 3) + 2 * (pl0 >> 2);
        int lane0 = (mrow & 7) * 4 + (pl0 & 3);
        a_addr[r] = (k16 * 5 + mt) * ATS + (j0 >> 1) * 128 + lane0 * 4 + (j0 & 1) * 2;
        a_ptr[r] = A + (size_t)m * lda + s * 4;
    }
    // B: 16 pair-rows x 32 n4 = 512 units -> unit tid, and tid+320 (tid<192)
    int b_addr[2];
    const float* b_ptr[2];
    int b_ok[2];
    #pragma unroll
    for (int r = 0; r < 2; r++) {
        int idx = tid + r * 320;
        b_ok[r] = (idx < 512);
        int p = idx >> 5;          // global pair 0..15
        int n4 = (idx & 31) * 4;
        int k16 = p >> 3, pl = p & 7;
        int nt = n4 >> 3, cg = n4 & 7;
        b_addr[r] = OFF_B + (k16 * 16 + nt) * BTS + (cg * 4 + (pl & 3)) * 4 + 2 * (pl >> 2);
        b_ptr[r] = Bg + (size_t)(2 * p) * ldb + n0 + n4;
    }

    float4 areg[2];
    float4 brow0[2], brow1[2];

    float acc[8][4];
    #pragma unroll
    for (int j = 0; j < 8; j++)
        #pragma unroll
        for (int i = 0; i < 4; i++) acc[j][i] = 0.0f;

    auto ldg_tile = [&](int k0) {
        #pragma unroll
        for (int r = 0; r < 2; r++)
            areg[r] = *reinterpret_cast<const float4*>(a_ptr[r] + k0);
        #pragma unroll
        for (int r = 0; r < 2; r++)
            if (b_ok[r]) {
                const float* bs = b_ptr[r] + (size_t)k0 * ldb;
                brow0[r] = *reinterpret_cast<const float4*>(bs);
                brow1[r] = *reinterpret_cast<const float4*>(bs + ldb);
            }
    };
    auto sts_tile = [&](int buf) {
        uint32_t* base = Sm + buf * BUF_U32;
        #pragma unroll
        for (int r = 0; r < 2; r++) {
            uint32_t h0, l0, h1, l1;
            split2(areg[r].x, areg[r].y, h0, l0);
            split2(areg[r].z, areg[r].w, h1, l1);
            *reinterpret_cast<uint2*>(base + a_addr[r]) = make_uint2(h0, l0);
            *reinterpret_cast<uint2*>(base + a_addr[r] + 4) = make_uint2(h1, l1);
        }
        #pragma unroll
        for (int r = 0; r < 2; r++)
            if (b_ok[r]) {
                const float* r0 = &brow0[r].x;
                const float* r1 = &brow1[r].x;
                #pragma unroll
                for (int i = 0; i < 4; i++) {
                    uint32_t h, l;
                    split2(r0[i], r1[i], h, l);
                    *reinterpret_cast<uint2*>(base + b_addr[r] + i * 16) = make_uint2(h, l);
                }
            }
    };

    // ---- prologue ----
    ldg_tile(kbase);
    sts_tile(0);
    if (ktiles > 1) ldg_tile(kbase + KT);
    __syncthreads();

    const int a_off = wm * ATS + lid * 4;
    const int b_off = OFF_B + wn * 8 * BTS + lid * 4;

    for (int j = 0; j < ktiles; j++) {
        const int buf = j & 1;
        // STS next tile first: MMAs below cover its latency. Safe: the sync at the
        // end of iter j-1 already ordered this buffer's previous readers.
        if (j + 1 < ktiles) sts_tile((j + 1) & 1);

        const uint32_t* S = Sm + buf * BUF_U32;
        #pragma unroll
        for (int q = 0; q < 2; q++) {
            const uint32_t* At = S + q * 5 * ATS + a_off;
            uint4 A0 = *reinterpret_cast<const uint4*>(At);
            uint4 A1 = *reinterpret_cast<const uint4*>(At + 128);
            const uint32_t* Bt = S + q * 16 * BTS + b_off;
            #pragma unroll
            for (int jf = 0; jf < 8; jf++) {
                uint4 Bv = *reinterpret_cast<const uint4*>(Bt + jf * BTS);
                mma_bf16(acc[jf], A0.x, A0.z, A1.x, A1.z, Bv.x, Bv.z);  // hi*hi
                mma_bf16(acc[jf], A0.x, A0.z, A1.x, A1.z, Bv.y, Bv.w);  // hi*lo
                mma_bf16(acc[jf], A0.y, A0.w, A1.y, A1.w, Bv.x, Bv.z);  // lo*hi
            }
        }

        if (j + 2 < ktiles) ldg_tile(kbase + (j + 2) * KT);
        __syncthreads();
    }

    // ---- epilogue: rows all < 80 by construction ----
    #pragma unroll
    for (int jf = 0; jf < 8; jf++) {
        const int n = n0 + wn * 64 + jf * 8 + 2 * c;
        #pragma unroll
        for (int h = 0; h < 2; h++) {
            const int m = wm * 16 + g + 8 * h;
            float2 v;
            v.x = acc[jf][2 * h + 0];
            v.y = acc[jf][2 * h + 1];
            if (GELU) { v.x = gelu_exact(v.x); v.y = gelu_exact(v.y); }
            *reinterpret_cast<float2*>(&Out[(size_t)m * ldo + n]) = v;
        }
    }
}

__global__ __launch_bounds__(320, 2)
void gemm1_kernel(const float* __restrict__ inputs, const int* __restrict__ y,
                  const float* __restrict__ w1)
{
    const int b = blockIdx.y;
    const int e = y[b] % En;
    gemm_core<true>(inputs + (size_t)b * Nn * Dn, Dn,
                    w1 + (size_t)e * Dn * Hn, Hn,
                    blockIdx.x * NT, 0, Dn / KT,
                    g_hidden + (size_t)b * CAP * Hn, Hn);
}

__global__ __launch_bounds__(320, 2)
void gemm2_kernel(const int* __restrict__ y, const float* __restrict__ w2)
{
    const int b = blockIdx.y;
    const int e = y[b] % En;
    const int split = blockIdx.z;
    gemm_core<false>(g_hidden + (size_t)b * CAP * Hn, Hn,
                     w2 + (size_t)e * Hn * Dn, Dn,
                     blockIdx.x * NT, split * (Hn / SPLITK), (Hn / SPLITK) / KT,
                     g_partial + ((size_t)split * Bn + b) * CAP * Dn, Dn);
}

// Sum split-K partials into out for tokens < CAP; zero otherwise.
__global__ __launch_bounds__(256) void reduce_kernel(float* __restrict__ out)
{
    const size_t idx4 = (size_t)blockIdx.x * blockDim.x + threadIdx.x;
    const size_t total4 = (size_t)Bn * Nn * Dn / 4;
    if (idx4 >= total4) return;
    const int per_b4 = Nn * Dn / 4;
    const int b = (int)(idx4 / per_b4);
    const int r = (int)(idx4 % per_b4);
    const int tok = r / (Dn / 4);
    const int d4 = r % (Dn / 4);

    float4 v = make_float4(0.f, 0.f, 0.f, 0.f);
    if (tok < CAP) {
        #pragma unroll
        for (int s = 0; s < SPLITK; s++) {
            const float4 p = *reinterpret_cast<const float4*>(
                &g_partial[(((size_t)s * Bn + b) * CAP + tok) * Dn + d4 * 4]);
            v.x += p.x; v.y += p.y; v.z += p.z; v.w += p.w;
        }
    }
    reinterpret_cast<float4*>(out)[idx4] = v;
}

extern "C" void kernel_launch(void* const* d_in, const int* in_sizes, int n_in,
                              void* d_out, int out_size) {
    const float* inputs = (const float*)d_in[0];   // (8, 1024, 1024) f32
    const int*   y      = (const int*)d_in[1];     // (8,) i32
    const float* w1     = (const float*)d_in[2];   // (16, 1024, 4096) f32
    const float* w2     = (const float*)d_in[3];   // (16, 4096, 1024) f32
    float* out = (float*)d_out;                    // (8, 1024, 1024) f32

    cudaFuncSetAttribute(gemm1_kernel, cudaFuncAttributeMaxDynamicSharedMemorySize, SMEM_BYTES);
    cudaFuncSetAttribute(gemm2_kernel, cudaFuncAttributeMaxDynamicSharedMemorySize, SMEM_BYTES);

    dim3 g1(Hn / NT, Bn);              // 32 x 8 = 256 CTAs
    gemm1_kernel<<<g1, 320, SMEM_BYTES>>>(inputs, y, w1);

    dim3 g2(Dn / NT, Bn, SPLITK);      // 8 x 8 x 4 = 256 CTAs
    gemm2_kernel<<<g2, 320, SMEM_BYTES>>>(y, w2);

    const size_t total4 = (size_t)Bn * Nn * Dn / 4;
    reduce_kernel<<<(unsigned)((total4 + 255) / 256), 256>>>(out);
}

// round 8
// speedup vs baseline: 1.3791x; 1.3791x over previous
#include <cuda_runtime.h>
#include <cstdint>
#include <math.h>

#define Bn 8
#define Nn 1024
#define Dn 1024
#define Hn 4096
#define En 16
#define CAP 80
#define SPLITK 4

#define NT 128      // block tile N
#define KT 32       // block tile K

// smem (u32 units), double buffered:
//   AH [80][20]  (k-pair u32, row stride 20 -> ldmatrix conflict-free) = 1600
//   AL [80][20]                                                        = 1600
//   BH [32][64]  (plain bf16 rows of 128 n, 16B-chunk ^ (k&7) swizzle) = 2048
//   BL [32][64]                                                        = 2048
#define APS 20
#define OFF_AH 0
#define OFF_AL 1600
#define OFF_BH 3200
#define OFF_BL 5248
#define BUF_U32 7296
#define SMEM_BYTES (2 * BUF_U32 * 4)   // 58368

__device__ float g_hidden[(size_t)Bn * CAP * Hn];
__device__ float g_partial[(size_t)SPLITK * Bn * CAP * Dn];

__device__ __forceinline__ float gelu_exact(float x) {
    return 0.5f * x * (1.0f + erff(x * 0.70710678118654752440f));
}
__device__ __forceinline__ uint32_t smem_u32(const void* p) {
    uint32_t a;
    asm("{ .reg .u64 t; cvta.to.shared.u64 t, %1; cvt.u32.u64 %0, t; }" : "=r"(a) : "l"(p));
    return a;
}

// Split two f32 into packed bf16x2 hi (truncated, x in low half) and lo (residual).
__device__ __forceinline__ void split2(float x, float y, uint32_t& hi, uint32_t& lo) {
    uint32_t bx = __float_as_uint(x), by = __float_as_uint(y);
    asm("prmt.b32 %0, %1, %2, 0x7632;" : "=r"(hi) : "r"(bx), "r"(by));
    float lx = x - __uint_as_float(bx & 0xFFFF0000u);
    float ly = y - __uint_as_float(by & 0xFFFF0000u);
    asm("cvt.rn.bf16x2.f32 %0, %1, %2;" : "=r"(lo) : "f"(ly), "f"(lx));
}

__device__ __forceinline__ void mma_bf16(
    float* acc, uint32_t a0, uint32_t a1, uint32_t a2, uint32_t a3,
    uint32_t b0, uint32_t b1)
{
    asm volatile(
        "mma.sync.aligned.m16n8k16.row.col.f32.bf16.bf16.f32 "
        "{%0,%1,%2,%3}, {%4,%5,%6,%7}, {%8,%9}, {%0,%1,%2,%3};"
        : "+f"(acc[0]), "+f"(acc[1]), "+f"(acc[2]), "+f"(acc[3])
        : "r"(a0), "r"(a1), "r"(a2), "r"(a3), "r"(b0), "r"(b1));
}

#define LDSM_X4(r0, r1, r2, r3, addr) \
    asm volatile("ldmatrix.sync.aligned.m8n8.x4.shared.b16 {%0,%1,%2,%3}, [%4];" \
        : "=r"(r0), "=r"(r1), "=r"(r2), "=r"(r3) : "r"(addr))
#define LDSM_X4T(r0, r1, r2, r3, addr) \
    asm volatile("ldmatrix.sync.aligned.m8n8.x4.trans.shared.b16 {%0,%1,%2,%3}, [%4];" \
        : "=r"(r0), "=r"(r1), "=r"(r2), "=r"(r3) : "r"(addr))

// ---------------------------------------------------------------------------
// Core: Out[0:80, n0:n0+128] = A[80 x K] * B[K x N] over k in
// [kbase, kbase+ktiles*32). 3-term bf16-split mma.sync + ldmatrix, fp32 accum.
// 320 threads = 10 warps (5 M x 2 N), warp tile 16x64.
// ---------------------------------------------------------------------------
template <bool GELU>
__device__ __forceinline__ void gemm_core(
    const float* __restrict__ A, int lda,
    const float* __restrict__ Bg, int ldb,
    int n0, int kbase, int ktiles,
    float* __restrict__ Out, int ldo)
{
    extern __shared__ uint32_t Sm[];
    const uint32_t su = smem_u32(Sm);
    const int tid = threadIdx.x;
    const int wid = tid >> 5;
    const int lid = tid & 31;
    const int wm = wid >> 1;        // 0..4
    const int wn = wid & 1;         // 0..1
    const int g = lid >> 2;         // 0..7
    const int c = lid & 3;          // 0..3

    // ---- producer mappings ----
    // A: 80 rows x 8 float4 = 640 units -> 2 per thread
    int a_m[2], a_s[2];
    #pragma unroll
    for (int r = 0; r < 2; r++) {
        int idx = tid + r * 320;
        a_m[r] = idx >> 3;         // 0..79
        a_s[r] = idx & 7;          // float4 within row
    }
    // B: 32 k-rows x 32 float4 = 1024 units -> 4 rounds (last partial)
    // u32 offset in plane: k*64 + ((n8 ^ (k&7)) << 2) + ((n4 & 4) >> 1)
    int b_k[4], b_n4[4], b_off[4], b_ok[4];
    #pragma unroll
    for (int r = 0; r < 4; r++) {
        int idx = tid + r * 320;
        b_ok[r] = (idx < 1024);
        int k = idx >> 5;
        int n4 = (idx & 31) * 4;
        b_k[r] = k; b_n4[r] = n4;
        b_off[r] = k * 64 + (((n4 >> 3) ^ (k & 7)) << 2) + ((n4 & 4) >> 1);
    }

    float4 areg[2], breg[4];

    float acc[8][4];
    #pragma unroll
    for (int j = 0; j < 8; j++)
        #pragma unroll
        for (int i = 0; i < 4; i++) acc[j][i] = 0.0f;

    auto ldg_tile = [&](int k0) {
        #pragma unroll
        for (int r = 0; r < 2; r++)
            areg[r] = *reinterpret_cast<const float4*>(
                &A[(size_t)a_m[r] * lda + k0 + a_s[r] * 4]);
        #pragma unroll
        for (int r = 0; r < 4; r++)
            if (b_ok[r])
                breg[r] = *reinterpret_cast<const float4*>(
                    &Bg[(size_t)(k0 + b_k[r]) * ldb + n0 + b_n4[r]]);
    };
    auto sts_tile = [&](int buf) {
        uint32_t* base = Sm + buf * BUF_U32;
        #pragma unroll
        for (int r = 0; r < 2; r++) {
            uint32_t h0, l0, h1, l1;
            split2(areg[r].x, areg[r].y, h0, l0);
            split2(areg[r].z, areg[r].w, h1, l1);
            int d = a_m[r] * APS + a_s[r] * 2;
            *reinterpret_cast<uint2*>(base + OFF_AH + d) = make_uint2(h0, h1);
            *reinterpret_cast<uint2*>(base + OFF_AL + d) = make_uint2(l0, l1);
        }
        #pragma unroll
        for (int r = 0; r < 4; r++)
            if (b_ok[r]) {
                uint32_t h0, l0, h1, l1;
                split2(breg[r].x, breg[r].y, h0, l0);
                split2(breg[r].z, breg[r].w, h1, l1);
                *reinterpret_cast<uint2*>(base + OFF_BH + b_off[r]) = make_uint2(h0, h1);
                *reinterpret_cast<uint2*>(base + OFF_BL + b_off[r]) = make_uint2(l0, l1);
            }
    };

    // ---- consumer ldmatrix addresses (byte offsets within a buffer) ----
    // A: lane -> row (wm*16 + (l&7) + 8*((l>>3)&1)), k-half chunk (l>>4)
    const int a_row = wm * 16 + (lid & 7) + ((lid >> 3) & 1) * 8;
    const uint32_t a_lds = (uint32_t)(a_row * APS + (lid >> 4) * 4) * 4;
    // B: lane -> k-row (l&15), n8 group (l>>4); group t covers n = wn*64+t*16
    const int b_krow = lid & 15;
    uint32_t b_lds[4];
    #pragma unroll
    for (int t = 0; t < 4; t++) {
        int chunk = (wn * 8 + t * 2 + (lid >> 4)) ^ (b_krow & 7);
        b_lds[t] = (uint32_t)(b_krow * 64 + chunk * 4) * 4;
    }

    // ---- prologue ----
    ldg_tile(kbase);
    sts_tile(0);
    if (ktiles > 1) ldg_tile(kbase + KT);
    __syncthreads();

    for (int j = 0; j < ktiles; j++) {
        const uint32_t bufb = su + (uint32_t)(j & 1) * (BUF_U32 * 4);

        #pragma unroll
        for (int q = 0; q < 2; q++) {
            uint32_t ah0, ah1, ah2, ah3, al0, al1, al2, al3;
            LDSM_X4(ah0, ah1, ah2, ah3, bufb + OFF_AH * 4 + a_lds + q * 32);
            LDSM_X4(al0, al1, al2, al3, bufb + OFF_AL * 4 + a_lds + q * 32);
            #pragma unroll
            for (int t = 0; t < 4; t++) {
                uint32_t bh0, bh1, bh2, bh3, bl0, bl1, bl2, bl3;
                const uint32_t boff = b_lds[t] + q * 4096;
                LDSM_X4T(bh0, bh1, bh2, bh3, bufb + OFF_BH * 4 + boff);
                LDSM_X4T(bl0, bl1, bl2, bl3, bufb + OFF_BL * 4 + boff);
                mma_bf16(acc[t * 2 + 0], ah0, ah1, ah2, ah3, bh0, bh1);
                mma_bf16(acc[t * 2 + 0], ah0, ah1, ah2, ah3, bl0, bl1);
                mma_bf16(acc[t * 2 + 0], al0, al1, al2, al3, bh0, bh1);
                mma_bf16(acc[t * 2 + 1], ah0, ah1, ah2, ah3, bh2, bh3);
                mma_bf16(acc[t * 2 + 1], ah0, ah1, ah2, ah3, bl2, bl3);
                mma_bf16(acc[t * 2 + 1], al0, al1, al2, al3, bh2, bh3);
            }
        }

        if (j + 1 < ktiles) {
            sts_tile((j + 1) & 1);
            if (j + 2 < ktiles) ldg_tile(kbase + (j + 2) * KT);
        }
        __syncthreads();
    }

    // ---- epilogue: rows all < 80 by construction ----
    #pragma unroll
    for (int jf = 0; jf < 8; jf++) {
        const int n = n0 + wn * 64 + jf * 8 + 2 * c;
        #pragma unroll
        for (int h = 0; h < 2; h++) {
            const int m = wm * 16 + g + 8 * h;
            float2 v;
            v.x = acc[jf][2 * h + 0];
            v.y = acc[jf][2 * h + 1];
            if (GELU) { v.x = gelu_exact(v.x); v.y = gelu_exact(v.y); }
            *reinterpret_cast<float2*>(&Out[(size_t)m * ldo + n]) = v;
        }
    }
}

__global__ __launch_bounds__(320, 2)
void gemm1_kernel(const float* __restrict__ inputs, const int* __restrict__ y,
                  const float* __restrict__ w1)
{
    const int b = blockIdx.y;
    const int e = y[b] % En;
    gemm_core<true>(inputs + (size_t)b * Nn * Dn, Dn,
                    w1 + (size_t)e * Dn * Hn, Hn,
                    blockIdx.x * NT, 0, Dn / KT,
                    g_hidden + (size_t)b * CAP * Hn, Hn);
}

__global__ __launch_bounds__(320, 2)
void gemm2_kernel(const int* __restrict__ y, const float* __restrict__ w2)
{
    const int b = blockIdx.y;
    const int e = y[b] % En;
    const int split = blockIdx.z;
    gemm_core<false>(g_hidden + (size_t)b * CAP * Hn, Hn,
                     w2 + (size_t)e * Hn * Dn, Dn,
                     blockIdx.x * NT, split * (Hn / SPLITK), (Hn / SPLITK) / KT,
                     g_partial + ((size_t)split * Bn + b) * CAP * Dn, Dn);
}

// Sum split-K partials into out for tokens < CAP; zero otherwise.
__global__ __launch_bounds__(256) void reduce_kernel(float* __restrict__ out)
{
    const size_t idx4 = (size_t)blockIdx.x * blockDim.x + threadIdx.x;
    const size_t total4 = (size_t)Bn * Nn * Dn / 4;
    if (idx4 >= total4) return;
    const int per_b4 = Nn * Dn / 4;
    const int b = (int)(idx4 / per_b4);
    const int r = (int)(idx4 % per_b4);
    const int tok = r / (Dn / 4);
    const int d4 = r % (Dn / 4);

    float4 v = make_float4(0.f, 0.f, 0.f, 0.f);
    if (tok < CAP) {
        #pragma unroll
        for (int s = 0; s < SPLITK; s++) {
            const float4 p = *reinterpret_cast<const float4*>(
                &g_partial[(((size_t)s * Bn + b) * CAP + tok) * Dn + d4 * 4]);
            v.x += p.x; v.y += p.y; v.z += p.z; v.w += p.w;
        }
    }
    reinterpret_cast<float4*>(out)[idx4] = v;
}

extern "C" void kernel_launch(void* const* d_in, const int* in_sizes, int n_in,
                              void* d_out, int out_size) {
    const float* inputs = (const float*)d_in[0];   // (8, 1024, 1024) f32
    const int*   y      = (const int*)d_in[1];     // (8,) i32
    const float* w1     = (const float*)d_in[2];   // (16, 1024, 4096) f32
    const float* w2     = (const float*)d_in[3];   // (16, 4096, 1024) f32
    float* out = (float*)d_out;                    // (8, 1024, 1024) f32

    cudaFuncSetAttribute(gemm1_kernel, cudaFuncAttributeMaxDynamicSharedMemorySize, SMEM_BYTES);
    cudaFuncSetAttribute(gemm2_kernel, cudaFuncAttributeMaxDynamicSharedMemorySize, SMEM_BYTES);

    dim3 g1(Hn / NT, Bn);              // 32 x 8 = 256 CTAs
    gemm1_kernel<<<g1, 320, SMEM_BYTES>>>(inputs, y, w1);

    dim3 g2(Dn / NT, Bn, SPLITK);      // 8 x 8 x 4 = 256 CTAs
    gemm2_kernel<<<g2, 320, SMEM_BYTES>>>(y, w2);

    const size_t total4 = (size_t)Bn * Nn * Dn / 4;
    reduce_kernel<<<(unsigned)((total4 + 255) / 256), 256>>>(out);
}